// round 11
// baseline (speedup 1.0000x reference)
#include <cuda_runtime.h>
#include <cuda_fp16.h>
#include <cstdint>

#define M_NODES 100000
#define M_PAD   100096      // 782 * 128
#define DSRC    128
#define DOUT    256
#define KA      256         // g_A cols: [dst | agg] fp16
#define MAX_E   600000
#define NSM     148

// -------- device scratch --------
__device__ __align__(16) int g_cnt[M_NODES];        // zero at every launch start
__device__ __align__(16) int g_off[M_NODES + 1];
__device__ __align__(16) int g_cur[M_NODES];
__device__ __align__(16) int g_csr[MAX_E];
__device__ int g_bar1, g_bar2;                      // reusable global barrier
__device__ __align__(16) __half g_A[(size_t)M_PAD * KA];   // 51.2 MB
__device__ __align__(16) __half g_B[KA * DOUT];            // [ke][o]

// --------------- launch 0: prepW + histogram ---------------------------
__global__ void k_prep(const float* __restrict__ W,
                       const int* __restrict__ ei, int E) {
    int t = blockIdx.x * blockDim.x + threadIdx.x;
    if (t < KA * DOUT) {
        int o  = t & (DOUT - 1);
        int ke = t >> 8;
        g_B[ke * DOUT + o] = __float2half_rn(W[o * 256 + ke]);
    }
    if (t < E) atomicAdd(&g_cnt[ei[E + t]], 1);
}

// --------------- launch 1: scan (block 0) + global barrier + fill ------
__global__ __launch_bounds__(1024) void k_scanfill(const int* __restrict__ ei,
                                                   int E) {
    __shared__ int warp_sums[32];
    const int tid = threadIdx.x;

    if (blockIdx.x == 0) {
        const int CH = (M_NODES + 1023) / 1024;
        int beg = tid * CH;
        int end = min(beg + CH, M_NODES);
        int s = 0;
        for (int i = beg; i < end; i++) s += g_cnt[i];
        int lane = tid & 31, wid = tid >> 5;
        int v = s;
#pragma unroll
        for (int d = 1; d < 32; d <<= 1) {
            int u = __shfl_up_sync(0xffffffffu, v, d);
            if (lane >= d) v += u;
        }
        if (lane == 31) warp_sums[wid] = v;
        __syncthreads();
        if (wid == 0) {
            int w = warp_sums[lane];
#pragma unroll
            for (int d = 1; d < 32; d <<= 1) {
                int u = __shfl_up_sync(0xffffffffu, w, d);
                if (lane >= d) w += u;
            }
            warp_sums[lane] = w;
        }
        __syncthreads();
        int ex = v - s + (wid ? warp_sums[wid - 1] : 0);
        int run = ex;
        for (int i = beg; i < end; i++) {
            g_off[i] = run;
            g_cur[i] = run;
            run += g_cnt[i];
            g_cnt[i] = 0;                  // restore invariant
        }
        if (tid == 1023) g_off[M_NODES] = run;
    }

    // ---- global barrier (all 148 CTAs resident) ----
    __syncthreads();
    __threadfence();
    if (tid == 0) {
        atomicAdd(&g_bar1, 1);
        while (atomicAdd(&g_bar1, 0) < NSM) { }
        int p = atomicAdd(&g_bar2, 1);
        if (p == NSM - 1) {                // last one out resets for next replay
            g_bar1 = 0;
            g_bar2 = 0;
            __threadfence();
        }
    }
    __syncthreads();

    // ---- fill phase: grid-strided over edges ----
    for (int e = blockIdx.x * 1024 + tid; e < E; e += NSM * 1024) {
        int s = ei[e];
        int d = ei[E + e];
        int pos = atomicAdd(&g_cur[d], 1);
        g_csr[pos] = s;
    }
}

// --------------- launch 2: gather --------------------------------------
__global__ void k_gather(const float* __restrict__ xs,
                         const float* __restrict__ xd) {
    int n = blockIdx.x * (blockDim.x >> 5) + (threadIdx.x >> 5);
    int lane = threadIdx.x & 31;
    if (n >= M_NODES) return;
    int beg = g_off[n];
    int end = g_off[n + 1];
    float4 acc = make_float4(0.f, 0.f, 0.f, 0.f);
    int e = beg;
    for (; e + 1 < end; e += 2) {
        int s0 = g_csr[e], s1 = g_csr[e + 1];
        float4 v0 = ((const float4*)(xs + (size_t)s0 * DSRC))[lane];
        float4 v1 = ((const float4*)(xs + (size_t)s1 * DSRC))[lane];
        acc.x += v0.x + v1.x; acc.y += v0.y + v1.y;
        acc.z += v0.z + v1.z; acc.w += v0.w + v1.w;
    }
    if (e < end) {
        int s0 = g_csr[e];
        float4 v0 = ((const float4*)(xs + (size_t)s0 * DSRC))[lane];
        acc.x += v0.x; acc.y += v0.y; acc.z += v0.z; acc.w += v0.w;
    }
    float inv = 1.0f / (float)max(end - beg, 1);
    acc.x *= inv; acc.y *= inv; acc.z *= inv; acc.w *= inv;
    float4 vd = ((const float4*)(xd + (size_t)n * DSRC))[lane];
    __half* row = g_A + (size_t)n * KA;
    __half2* pd = (__half2*)(row + lane * 4);
    pd[0] = __floats2half2_rn(vd.x, vd.y);
    pd[1] = __floats2half2_rn(vd.z, vd.w);
    __half2* pa = (__half2*)(row + 128 + lane * 4);
    pa[0] = __floats2half2_rn(acc.x, acc.y);
    pa[1] = __floats2half2_rn(acc.z, acc.w);
}

// --------------- launch 3: GEMM (exact R7 config, 287.8us baseline) ----
#define BM 128
#define BN 256
#define BK 64
#define NT 512
#define NSTAGE 3
#define NCH (KA / BK)              // 4
#define SA_STAGE (BM * BK)
#define SB_STAGE (BK * BN)
#define SMEM_BYTES (NSTAGE * (SA_STAGE + SB_STAGE) * 2)   // 144KB

__device__ __forceinline__ void cp16(void* smem_dst, const void* gsrc) {
    uint32_t s = (uint32_t)__cvta_generic_to_shared(smem_dst);
    asm volatile("cp.async.cg.shared.global [%0], [%1], 16;" :: "r"(s), "l"(gsrc));
}

__global__ __launch_bounds__(NT) void k_gemm(const float* __restrict__ bias,
                                             float* __restrict__ out) {
    extern __shared__ __align__(16) __half smem[];
    __half* sA = smem;
    __half* sB = smem + NSTAGE * SA_STAGE;

    const int tid  = threadIdx.x;
    const int lane = tid & 31;
    const int warp = tid >> 5;
    const int wm   = warp >> 2;
    const int wn   = warp & 3;
    const int m0   = blockIdx.x * BM;

    auto load_stage = [&](int kc, int st) {
        int ka = kc * BK;
        __half* sa = sA + st * SA_STAGE;
#pragma unroll
        for (int i = 0; i < 2; i++) {
            int c = tid + i * NT;
            int rowA = c >> 3, cA = c & 7;
            int ph = cA ^ (rowA & 7);
            cp16(sa + rowA * BK + ph * 8,
                 g_A + (size_t)(m0 + rowA) * KA + ka + cA * 8);
        }
        __half* sb = sB + st * SB_STAGE;
#pragma unroll
        for (int i = 0; i < 4; i++) {
            int c = tid + i * NT;
            int rowB = c >> 5, cB = c & 31;
            int ph = (cB & ~7) | ((cB ^ rowB) & 7);
            cp16(sb + rowB * BN + ph * 8,
                 g_B + (size_t)(ka + rowB) * DOUT + cB * 8);
        }
    };

    float acc[2][8][4];
#pragma unroll
    for (int i = 0; i < 2; i++)
#pragma unroll
        for (int j = 0; j < 8; j++)
#pragma unroll
            for (int k = 0; k < 4; k++) acc[i][j][k] = 0.f;

    load_stage(0, 0);
    asm volatile("cp.async.commit_group;");
    load_stage(1, 1);
    asm volatile("cp.async.commit_group;");

    for (int kc = 0; kc < NCH; kc++) {
        __syncthreads();
        if (kc + 2 < NCH) load_stage(kc + 2, (kc + 2) % NSTAGE);
        asm volatile("cp.async.commit_group;");
        asm volatile("cp.async.wait_group 2;");
        __syncthreads();

        const __half* sa = sA + (kc % NSTAGE) * SA_STAGE;
        const __half* sb = sB + (kc % NSTAGE) * SB_STAGE;

#pragma unroll
        for (int ks = 0; ks < 4; ks++) {
            uint32_t a[2][4], b[8][2];
#pragma unroll
            for (int mf = 0; mf < 2; mf++) {
                int row = wm * 32 + mf * 16 + (lane & 15);
                int c   = ks * 2 + (lane >> 4);
                int ph  = c ^ (row & 7);
                uint32_t addr = (uint32_t)__cvta_generic_to_shared(
                    sa + row * BK + ph * 8);
                asm volatile("ldmatrix.sync.aligned.m8n8.x4.shared.b16 {%0,%1,%2,%3}, [%4];"
                             : "=r"(a[mf][0]), "=r"(a[mf][1]), "=r"(a[mf][2]), "=r"(a[mf][3])
                             : "r"(addr));
            }
#pragma unroll
            for (int nf = 0; nf < 8; nf++) {
                int row = ks * 16 + (lane & 15);
                int cB  = wn * 8 + nf;
                int ph  = (cB & ~7) | ((cB ^ row) & 7);
                uint32_t addr = (uint32_t)__cvta_generic_to_shared(
                    sb + row * BN + ph * 8);
                asm volatile("ldmatrix.sync.aligned.m8n8.x2.trans.shared.b16 {%0,%1}, [%2];"
                             : "=r"(b[nf][0]), "=r"(b[nf][1]) : "r"(addr));
            }
#pragma unroll
            for (int mf = 0; mf < 2; mf++)
#pragma unroll
                for (int nf = 0; nf < 8; nf++) {
                    asm volatile(
                        "mma.sync.aligned.m16n8k16.row.col.f32.f16.f16.f32 "
                        "{%0,%1,%2,%3},{%4,%5,%6,%7},{%8,%9},{%0,%1,%2,%3};"
                        : "+f"(acc[mf][nf][0]), "+f"(acc[mf][nf][1]),
                          "+f"(acc[mf][nf][2]), "+f"(acc[mf][nf][3])
                        : "r"(a[mf][0]), "r"(a[mf][1]), "r"(a[mf][2]), "r"(a[mf][3]),
                          "r"(b[nf][0]), "r"(b[nf][1]));
                }
        }
    }

#pragma unroll
    for (int mf = 0; mf < 2; mf++) {
        int r0 = m0 + wm * 32 + mf * 16 + (lane >> 2);
#pragma unroll
        for (int nf = 0; nf < 8; nf++) {
            int c = wn * 64 + nf * 8 + (lane & 3) * 2;
            float b0 = bias[c], b1 = bias[c + 1];
            if (r0 < M_NODES) {
                out[(size_t)r0 * DOUT + c]     = fmaxf(acc[mf][nf][0] + b0, 0.f);
                out[(size_t)r0 * DOUT + c + 1] = fmaxf(acc[mf][nf][1] + b1, 0.f);
            }
            int r1 = r0 + 8;
            if (r1 < M_NODES) {
                out[(size_t)r1 * DOUT + c]     = fmaxf(acc[mf][nf][2] + b0, 0.f);
                out[(size_t)r1 * DOUT + c + 1] = fmaxf(acc[mf][nf][3] + b1, 0.f);
            }
        }
    }
}

// ---------------------------------------------------------------------
extern "C" void kernel_launch(void* const* d_in, const int* in_sizes, int n_in,
                              void* d_out, int out_size) {
    const float* x_src = (const float*)d_in[0];
    const float* x_dst = (const float*)d_in[1];
    const int*   ei    = (const int*)d_in[2];
    const float* W     = (const float*)d_in[3];
    const float* b     = (const float*)d_in[4];
    float*       out   = (float*)d_out;
    int E = in_sizes[2] / 2;

    cudaFuncSetAttribute(k_gemm, cudaFuncAttributeMaxDynamicSharedMemorySize,
                         SMEM_BYTES);

    k_prep<<<(E + 255) / 256, 256>>>(W, ei, E);                   // 0
    k_scanfill<<<NSM, 1024>>>(ei, E);                             // 1
    k_gather<<<(M_NODES * 32 + 255) / 256, 256>>>(x_src, x_dst);  // 2
    k_gemm<<<M_PAD / BM, NT, SMEM_BYTES>>>(b, out);               // 3 (profiled)
}

// round 12
// speedup vs baseline: 1.0226x; 1.0226x over previous
#include <cuda_runtime.h>
#include <cuda_fp16.h>
#include <cstdint>

#define M_NODES 100000
#define M_PAD   100096      // 782 * 128
#define DSRC    128
#define DOUT    256
#define KA      256         // g_A cols: [dst | agg] fp16
#define MAX_E   600000

// -------- device scratch --------
__device__ __align__(16) int g_cnt[M_NODES];        // zero at every launch start
__device__ __align__(16) int g_off[M_NODES + 1];
__device__ __align__(16) int g_cur[M_NODES];
__device__ __align__(16) int g_csr[MAX_E];
__device__ __align__(16) __half g_A[(size_t)M_PAD * KA];   // 51.2 MB
__device__ __align__(16) __half g_B[KA * DOUT];            // [ke][o]

// --------------- launch 0: prepW + histogram ---------------------------
__global__ void k_prep(const float* __restrict__ W,
                       const int* __restrict__ ei, int E) {
    int t = blockIdx.x * blockDim.x + threadIdx.x;
    if (t < KA * DOUT) {
        int o  = t & (DOUT - 1);
        int ke = t >> 8;
        g_B[ke * DOUT + o] = __float2half_rn(W[o * 256 + ke]);
    }
    if (t < E) atomicAdd(&g_cnt[ei[E + t]], 1);
}

// --------------- launch 1: scan (self-zeroing) --------------------------
__global__ __launch_bounds__(1024) void k_scan() {
    __shared__ int warp_sums[32];
    const int tid = threadIdx.x;
    const int CH = (M_NODES + 1023) / 1024;
    int beg = tid * CH;
    int end = min(beg + CH, M_NODES);
    int s = 0;
    for (int i = beg; i < end; i++) s += g_cnt[i];
    int lane = tid & 31, wid = tid >> 5;
    int v = s;
#pragma unroll
    for (int d = 1; d < 32; d <<= 1) {
        int u = __shfl_up_sync(0xffffffffu, v, d);
        if (lane >= d) v += u;
    }
    if (lane == 31) warp_sums[wid] = v;
    __syncthreads();
    if (wid == 0) {
        int w = warp_sums[lane];
#pragma unroll
        for (int d = 1; d < 32; d <<= 1) {
            int u = __shfl_up_sync(0xffffffffu, w, d);
            if (lane >= d) w += u;
        }
        warp_sums[lane] = w;
    }
    __syncthreads();
    int ex = v - s + (wid ? warp_sums[wid - 1] : 0);
    int run = ex;
    for (int i = beg; i < end; i++) {
        g_off[i] = run;
        g_cur[i] = run;
        run += g_cnt[i];
        g_cnt[i] = 0;              // restore invariant for next replay
    }
    if (tid == 1023) g_off[M_NODES] = run;
}

// --------------- launch 2: CSR fill -------------------------------------
__global__ void k_fill(const int* __restrict__ ei, int E) {
    int t = blockIdx.x * blockDim.x + threadIdx.x;
    if (t >= E) return;
    int s = ei[t];
    int d = ei[E + t];
    int pos = atomicAdd(&g_cur[d], 1);
    g_csr[pos] = s;
}

// --------------- launch 3: gather (profiled slot) -----------------------
__global__ void k_gather(const float* __restrict__ xs,
                         const float* __restrict__ xd) {
    int n = blockIdx.x * (blockDim.x >> 5) + (threadIdx.x >> 5);
    int lane = threadIdx.x & 31;
    if (n >= M_NODES) return;
    int beg = g_off[n];
    int end = g_off[n + 1];
    float4 acc = make_float4(0.f, 0.f, 0.f, 0.f);
    int e = beg;
    for (; e + 1 < end; e += 2) {
        int s0 = g_csr[e], s1 = g_csr[e + 1];
        float4 v0 = ((const float4*)(xs + (size_t)s0 * DSRC))[lane];
        float4 v1 = ((const float4*)(xs + (size_t)s1 * DSRC))[lane];
        acc.x += v0.x + v1.x; acc.y += v0.y + v1.y;
        acc.z += v0.z + v1.z; acc.w += v0.w + v1.w;
    }
    if (e < end) {
        int s0 = g_csr[e];
        float4 v0 = ((const float4*)(xs + (size_t)s0 * DSRC))[lane];
        acc.x += v0.x; acc.y += v0.y; acc.z += v0.z; acc.w += v0.w;
    }
    float inv = 1.0f / (float)max(end - beg, 1);
    acc.x *= inv; acc.y *= inv; acc.z *= inv; acc.w *= inv;
    float4 vd = ((const float4*)(xd + (size_t)n * DSRC))[lane];
    __half* row = g_A + (size_t)n * KA;
    __half2* pd = (__half2*)(row + lane * 4);
    pd[0] = __floats2half2_rn(vd.x, vd.y);
    pd[1] = __floats2half2_rn(vd.z, vd.w);
    __half2* pa = (__half2*)(row + 128 + lane * 4);
    pa[0] = __floats2half2_rn(acc.x, acc.y);
    pa[1] = __floats2half2_rn(acc.z, acc.w);
}

// --------------- launch 4: GEMM, 2 CTAs/SM ------------------------------
#define BM 128
#define BN 128
#define BK 64
#define NT 256
#define NSTAGE 3
#define NCH (KA / BK)              // 4
#define SA_STAGE (BM * BK)         // 8192 elems = 16KB
#define SB_STAGE (BK * BN)         // 8192 elems = 16KB
#define SMEM_BYTES (NSTAGE * (SA_STAGE + SB_STAGE) * 2)   // 96KB

__device__ __forceinline__ void cp16(void* smem_dst, const void* gsrc) {
    uint32_t s = (uint32_t)__cvta_generic_to_shared(smem_dst);
    asm volatile("cp.async.cg.shared.global [%0], [%1], 16;" :: "r"(s), "l"(gsrc));
}

__global__ __launch_bounds__(NT, 2) void k_gemm(const float* __restrict__ bias,
                                                float* __restrict__ out) {
    extern __shared__ __align__(16) __half smem[];
    __half* sA = smem;                         // [NSTAGE][128][64]
    __half* sB = smem + NSTAGE * SA_STAGE;     // [NSTAGE][64][128]

    const int tid  = threadIdx.x;
    const int lane = tid & 31;
    const int warp = tid >> 5;       // 0..7
    const int wm   = warp >> 1;      // 0..3 -> 32 rows
    const int wn   = warp & 1;       // 0..1 -> 64 cols
    const int m0   = blockIdx.x * BM;
    const int n0   = blockIdx.y * BN;

    auto load_stage = [&](int kc, int st) {
        int ka = kc * BK;
        __half* sa = sA + st * SA_STAGE;
#pragma unroll
        for (int i = 0; i < 4; i++) {          // A: 1024 16B chunks / 256 thr
            int c = tid + i * NT;
            int rowA = c >> 3, cA = c & 7;
            int ph = cA ^ (rowA & 7);
            cp16(sa + rowA * BK + ph * 8,
                 g_A + (size_t)(m0 + rowA) * KA + ka + cA * 8);
        }
        __half* sb = sB + st * SB_STAGE;
#pragma unroll
        for (int i = 0; i < 4; i++) {          // B: 1024 16B chunks / 256 thr
            int c = tid + i * NT;
            int rowB = c >> 4, cB = c & 15;
            int ph = (cB & ~7) | ((cB ^ rowB) & 7);
            cp16(sb + rowB * BN + ph * 8,
                 g_B + (size_t)(ka + rowB) * DOUT + n0 + cB * 8);
        }
    };

    float acc[2][8][4];
#pragma unroll
    for (int i = 0; i < 2; i++)
#pragma unroll
        for (int j = 0; j < 8; j++)
#pragma unroll
            for (int k = 0; k < 4; k++) acc[i][j][k] = 0.f;

    load_stage(0, 0);
    asm volatile("cp.async.commit_group;");
    load_stage(1, 1);
    asm volatile("cp.async.commit_group;");

    for (int kc = 0; kc < NCH; kc++) {
        __syncthreads();
        if (kc + 2 < NCH) load_stage(kc + 2, (kc + 2) % NSTAGE);
        asm volatile("cp.async.commit_group;");
        asm volatile("cp.async.wait_group 2;");
        __syncthreads();

        const __half* sa = sA + (kc % NSTAGE) * SA_STAGE;
        const __half* sb = sB + (kc % NSTAGE) * SB_STAGE;

#pragma unroll
        for (int ks = 0; ks < 4; ks++) {
            uint32_t a[2][4], b[8][2];
#pragma unroll
            for (int mf = 0; mf < 2; mf++) {
                int row = wm * 32 + mf * 16 + (lane & 15);
                int c   = ks * 2 + (lane >> 4);
                int ph  = c ^ (row & 7);
                uint32_t addr = (uint32_t)__cvta_generic_to_shared(
                    sa + row * BK + ph * 8);
                asm volatile("ldmatrix.sync.aligned.m8n8.x4.shared.b16 {%0,%1,%2,%3}, [%4];"
                             : "=r"(a[mf][0]), "=r"(a[mf][1]), "=r"(a[mf][2]), "=r"(a[mf][3])
                             : "r"(addr));
            }
#pragma unroll
            for (int nf = 0; nf < 8; nf++) {
                int row = ks * 16 + (lane & 15);
                int cB  = wn * 8 + nf;
                int ph  = (cB & ~7) | ((cB ^ row) & 7);
                uint32_t addr = (uint32_t)__cvta_generic_to_shared(
                    sb + row * BN + ph * 8);
                asm volatile("ldmatrix.sync.aligned.m8n8.x2.trans.shared.b16 {%0,%1}, [%2];"
                             : "=r"(b[nf][0]), "=r"(b[nf][1]) : "r"(addr));
            }
#pragma unroll
            for (int mf = 0; mf < 2; mf++)
#pragma unroll
                for (int nf = 0; nf < 8; nf++) {
                    asm volatile(
                        "mma.sync.aligned.m16n8k16.row.col.f32.f16.f16.f32 "
                        "{%0,%1,%2,%3},{%4,%5,%6,%7},{%8,%9},{%0,%1,%2,%3};"
                        : "+f"(acc[mf][nf][0]), "+f"(acc[mf][nf][1]),
                          "+f"(acc[mf][nf][2]), "+f"(acc[mf][nf][3])
                        : "r"(a[mf][0]), "r"(a[mf][1]), "r"(a[mf][2]), "r"(a[mf][3]),
                          "r"(b[nf][0]), "r"(b[nf][1]));
                }
        }
    }

    // ---- epilogue: bias + ReLU ----
#pragma unroll
    for (int mf = 0; mf < 2; mf++) {
        int r0 = m0 + wm * 32 + mf * 16 + (lane >> 2);
#pragma unroll
        for (int nf = 0; nf < 8; nf++) {
            int c = n0 + wn * 64 + nf * 8 + (lane & 3) * 2;
            float b0 = bias[c], b1 = bias[c + 1];
            if (r0 < M_NODES) {
                out[(size_t)r0 * DOUT + c]     = fmaxf(acc[mf][nf][0] + b0, 0.f);
                out[(size_t)r0 * DOUT + c + 1] = fmaxf(acc[mf][nf][1] + b1, 0.f);
            }
            int r1 = r0 + 8;
            if (r1 < M_NODES) {
                out[(size_t)r1 * DOUT + c]     = fmaxf(acc[mf][nf][2] + b0, 0.f);
                out[(size_t)r1 * DOUT + c + 1] = fmaxf(acc[mf][nf][3] + b1, 0.f);
            }
        }
    }
}

// ---------------------------------------------------------------------
extern "C" void kernel_launch(void* const* d_in, const int* in_sizes, int n_in,
                              void* d_out, int out_size) {
    const float* x_src = (const float*)d_in[0];
    const float* x_dst = (const float*)d_in[1];
    const int*   ei    = (const int*)d_in[2];
    const float* W     = (const float*)d_in[3];
    const float* b     = (const float*)d_in[4];
    float*       out   = (float*)d_out;
    int E = in_sizes[2] / 2;

    cudaFuncSetAttribute(k_gemm, cudaFuncAttributeMaxDynamicSharedMemorySize,
                         SMEM_BYTES);

    k_prep<<<(E + 255) / 256, 256>>>(W, ei, E);                   // 0
    k_scan<<<1, 1024>>>();                                        // 1
    k_fill<<<(E + 255) / 256, 256>>>(ei, E);                      // 2
    k_gather<<<(M_NODES * 32 + 255) / 256, 256>>>(x_src, x_dst);  // 3 (profiled)
    dim3 grid(M_PAD / BM, DOUT / BN);
    k_gemm<<<grid, NT, SMEM_BYTES>>>(b, out);                     // 4
}

// round 13
// speedup vs baseline: 1.1694x; 1.1436x over previous
#include <cuda_runtime.h>
#include <cuda_fp16.h>
#include <cstdint>

#define M_NODES 100000
#define M_PAD   100096      // 782 * 128
#define DSRC    128
#define DOUT    256
#define KA      256         // g_A cols: [dst | agg] fp16
#define MAX_E   600000

// -------- device scratch --------
__device__ __align__(16) int g_cnt[M_NODES];
__device__ __align__(16) int g_off[M_NODES];
__device__ __align__(16) int g_cur[M_NODES];
__device__ __align__(16) int g_csr[MAX_E];
__device__ __align__(16) __half g_A[(size_t)M_PAD * KA];   // 51.2 MB
__device__ __align__(16) __half g_B[KA * DOUT];            // [ke][o] 128KB

// ------------------------- CSR build (R7 verbatim) --------------------
__global__ void k_zero() {
    int i = blockIdx.x * blockDim.x + threadIdx.x;
    if (i < M_NODES) g_cnt[i] = 0;
}

__global__ void k_hist(const int* __restrict__ ei, int E) {
    int t = blockIdx.x * blockDim.x + threadIdx.x;
    if (t >= E) return;
    atomicAdd(&g_cnt[ei[E + t]], 1);
}

__global__ __launch_bounds__(1024) void k_scan() {
    __shared__ int warp_sums[32];
    const int tid = threadIdx.x;
    const int CH = (M_NODES + 1023) / 1024;
    int beg = tid * CH;
    int end = min(beg + CH, M_NODES);
    int s = 0;
    for (int i = beg; i < end; i++) s += g_cnt[i];
    int lane = tid & 31, wid = tid >> 5;
    int v = s;
#pragma unroll
    for (int d = 1; d < 32; d <<= 1) {
        int u = __shfl_up_sync(0xffffffffu, v, d);
        if (lane >= d) v += u;
    }
    if (lane == 31) warp_sums[wid] = v;
    __syncthreads();
    if (wid == 0) {
        int w = warp_sums[lane];
#pragma unroll
        for (int d = 1; d < 32; d <<= 1) {
            int u = __shfl_up_sync(0xffffffffu, w, d);
            if (lane >= d) w += u;
        }
        warp_sums[lane] = w;
    }
    __syncthreads();
    int ex = v - s + (wid ? warp_sums[wid - 1] : 0);
    int run = ex;
    for (int i = beg; i < end; i++) {
        g_off[i] = run;
        g_cur[i] = run;
        run += g_cnt[i];
    }
}

__global__ void k_fill(const int* __restrict__ ei, int E) {
    int t = blockIdx.x * blockDim.x + threadIdx.x;
    if (t >= E) return;
    int s = ei[t];
    int d = ei[E + t];
    int pos = atomicAdd(&g_cur[d], 1);
    g_csr[pos] = s;
}

// W [256 out, 256 in] fp32 -> g_B [256 ke][256 o] fp16 (R7 verbatim)
__global__ void k_prepW(const float* __restrict__ W) {
    int t = blockIdx.x * blockDim.x + threadIdx.x;
    if (t >= KA * DOUT) return;
    int o  = t & (DOUT - 1);
    int ke = t >> 8;
    g_B[ke * DOUT + o] = __float2half_rn(W[o * 256 + ke]);
}

// ------------------------- gather (R7 verbatim) ------------------------
__global__ void k_gather(const float* __restrict__ xs,
                         const float* __restrict__ xd) {
    int n = blockIdx.x * (blockDim.x >> 5) + (threadIdx.x >> 5);
    int lane = threadIdx.x & 31;
    if (n >= M_NODES) return;
    int beg = g_off[n];
    int end = beg + g_cnt[n];
    float4 acc = make_float4(0.f, 0.f, 0.f, 0.f);
    int e = beg;
    for (; e + 1 < end; e += 2) {
        int s0 = g_csr[e], s1 = g_csr[e + 1];
        float4 v0 = ((const float4*)(xs + (size_t)s0 * DSRC))[lane];
        float4 v1 = ((const float4*)(xs + (size_t)s1 * DSRC))[lane];
        acc.x += v0.x + v1.x; acc.y += v0.y + v1.y;
        acc.z += v0.z + v1.z; acc.w += v0.w + v1.w;
    }
    if (e < end) {
        int s0 = g_csr[e];
        float4 v0 = ((const float4*)(xs + (size_t)s0 * DSRC))[lane];
        acc.x += v0.x; acc.y += v0.y; acc.z += v0.z; acc.w += v0.w;
    }
    float inv = 1.0f / (float)max(end - beg, 1);
    acc.x *= inv; acc.y *= inv; acc.z *= inv; acc.w *= inv;
    float4 vd = ((const float4*)(xd + (size_t)n * DSRC))[lane];
    __half* row = g_A + (size_t)n * KA;
    __half2* pd = (__half2*)(row + lane * 4);
    pd[0] = __floats2half2_rn(vd.x, vd.y);
    pd[1] = __floats2half2_rn(vd.z, vd.w);
    __half2* pa = (__half2*)(row + 128 + lane * 4);
    pa[0] = __floats2half2_rn(acc.x, acc.y);
    pa[1] = __floats2half2_rn(acc.z, acc.w);
}

// ------------- GEMM: R7 geometry, single-sync 3-stage pipeline ---------
#define BM 128
#define BN 256
#define BK 64
#define NT 512
#define NSTAGE 3
#define NCH (KA / BK)              // 4
#define SA_STAGE (BM * BK)
#define SB_STAGE (BK * BN)
#define SMEM_BYTES (NSTAGE * (SA_STAGE + SB_STAGE) * 2)   // 144KB

__device__ __forceinline__ void cp16(void* smem_dst, const void* gsrc) {
    uint32_t s = (uint32_t)__cvta_generic_to_shared(smem_dst);
    asm volatile("cp.async.cg.shared.global [%0], [%1], 16;" :: "r"(s), "l"(gsrc));
}

__global__ __launch_bounds__(NT) void k_gemm(const float* __restrict__ bias,
                                             float* __restrict__ out) {
    extern __shared__ __align__(16) __half smem[];
    __half* sA = smem;                         // [NSTAGE][128][64]
    __half* sB = smem + NSTAGE * SA_STAGE;     // [NSTAGE][64][256]

    const int tid  = threadIdx.x;
    const int lane = tid & 31;
    const int warp = tid >> 5;
    const int wm   = warp >> 2;
    const int wn   = warp & 3;
    const int m0   = blockIdx.x * BM;

    auto load_stage = [&](int kc, int st) {
        int ka = kc * BK;
        __half* sa = sA + st * SA_STAGE;
#pragma unroll
        for (int i = 0; i < 2; i++) {
            int c = tid + i * NT;
            int rowA = c >> 3, cA = c & 7;
            int ph = cA ^ (rowA & 7);
            cp16(sa + rowA * BK + ph * 8,
                 g_A + (size_t)(m0 + rowA) * KA + ka + cA * 8);
        }
        __half* sb = sB + st * SB_STAGE;
#pragma unroll
        for (int i = 0; i < 4; i++) {
            int c = tid + i * NT;
            int rowB = c >> 5, cB = c & 31;
            int ph = (cB & ~7) | ((cB ^ rowB) & 7);
            cp16(sb + rowB * BN + ph * 8,
                 g_B + (size_t)(ka + rowB) * DOUT + cB * 8);
        }
    };

    float acc[2][8][4];
#pragma unroll
    for (int i = 0; i < 2; i++)
#pragma unroll
        for (int j = 0; j < 8; j++)
#pragma unroll
            for (int k = 0; k < 4; k++) acc[i][j][k] = 0.f;

    load_stage(0, 0);
    asm volatile("cp.async.commit_group;");
    load_stage(1, 1);
    asm volatile("cp.async.commit_group;");

#pragma unroll
    for (int kc = 0; kc < NCH; kc++) {
        asm volatile("cp.async.wait_group 1;");   // stage kc complete
        __syncthreads();                          // all warps done with slot (kc-1)%3
        if (kc + 2 < NCH) load_stage(kc + 2, (kc + 2) % NSTAGE);
        asm volatile("cp.async.commit_group;");   // uniform group accounting

        const __half* sa = sA + (kc % NSTAGE) * SA_STAGE;
        const __half* sb = sB + (kc % NSTAGE) * SB_STAGE;

#pragma unroll
        for (int ks = 0; ks < 4; ks++) {
            uint32_t a[2][4], b[8][2];
#pragma unroll
            for (int mf = 0; mf < 2; mf++) {
                int row = wm * 32 + mf * 16 + (lane & 15);
                int c   = ks * 2 + (lane >> 4);
                int ph  = c ^ (row & 7);
                uint32_t addr = (uint32_t)__cvta_generic_to_shared(
                    sa + row * BK + ph * 8);
                asm volatile("ldmatrix.sync.aligned.m8n8.x4.shared.b16 {%0,%1,%2,%3}, [%4];"
                             : "=r"(a[mf][0]), "=r"(a[mf][1]), "=r"(a[mf][2]), "=r"(a[mf][3])
                             : "r"(addr));
            }
#pragma unroll
            for (int nf = 0; nf < 8; nf++) {
                int row = ks * 16 + (lane & 15);
                int cB  = wn * 8 + nf;
                int ph  = (cB & ~7) | ((cB ^ row) & 7);
                uint32_t addr = (uint32_t)__cvta_generic_to_shared(
                    sb + row * BN + ph * 8);
                asm volatile("ldmatrix.sync.aligned.m8n8.x2.trans.shared.b16 {%0,%1}, [%2];"
                             : "=r"(b[nf][0]), "=r"(b[nf][1]) : "r"(addr));
            }
#pragma unroll
            for (int mf = 0; mf < 2; mf++)
#pragma unroll
                for (int nf = 0; nf < 8; nf++) {
                    asm volatile(
                        "mma.sync.aligned.m16n8k16.row.col.f32.f16.f16.f32 "
                        "{%0,%1,%2,%3},{%4,%5,%6,%7},{%8,%9},{%0,%1,%2,%3};"
                        : "+f"(acc[mf][nf][0]), "+f"(acc[mf][nf][1]),
                          "+f"(acc[mf][nf][2]), "+f"(acc[mf][nf][3])
                        : "r"(a[mf][0]), "r"(a[mf][1]), "r"(a[mf][2]), "r"(a[mf][3]),
                          "r"(b[nf][0]), "r"(b[nf][1]));
                }
        }
    }

    // ---- epilogue: bias + ReLU ----
#pragma unroll
    for (int mf = 0; mf < 2; mf++) {
        int r0 = m0 + wm * 32 + mf * 16 + (lane >> 2);
#pragma unroll
        for (int nf = 0; nf < 8; nf++) {
            int c = wn * 64 + nf * 8 + (lane & 3) * 2;
            float b0 = bias[c], b1 = bias[c + 1];
            if (r0 < M_NODES) {
                out[(size_t)r0 * DOUT + c]     = fmaxf(acc[mf][nf][0] + b0, 0.f);
                out[(size_t)r0 * DOUT + c + 1] = fmaxf(acc[mf][nf][1] + b1, 0.f);
            }
            int r1 = r0 + 8;
            if (r1 < M_NODES) {
                out[(size_t)r1 * DOUT + c]     = fmaxf(acc[mf][nf][2] + b0, 0.f);
                out[(size_t)r1 * DOUT + c + 1] = fmaxf(acc[mf][nf][3] + b1, 0.f);
            }
        }
    }
}

// ---------------------------------------------------------------------
extern "C" void kernel_launch(void* const* d_in, const int* in_sizes, int n_in,
                              void* d_out, int out_size) {
    const float* x_src = (const float*)d_in[0];
    const float* x_dst = (const float*)d_in[1];
    const int*   ei    = (const int*)d_in[2];
    const float* W     = (const float*)d_in[3];
    const float* b     = (const float*)d_in[4];
    float*       out   = (float*)d_out;
    int E = in_sizes[2] / 2;

    cudaFuncSetAttribute(k_gemm, cudaFuncAttributeMaxDynamicSharedMemorySize,
                         SMEM_BYTES);

    k_zero<<<(M_NODES + 255) / 256, 256>>>();
    k_hist<<<(E + 255) / 256, 256>>>(ei, E);
    k_scan<<<1, 1024>>>();
    k_fill<<<(E + 255) / 256, 256>>>(ei, E);
    k_prepW<<<(KA * DOUT + 255) / 256, 256>>>(W);
    k_gather<<<(M_NODES * 32 + 255) / 256, 256>>>(x_src, x_dst);
    k_gemm<<<M_PAD / BM, NT, SMEM_BYTES>>>(b, out);
}